// round 4
// baseline (speedup 1.0000x reference)
#include <cuda_runtime.h>

#define Bn 4
#define Cn 64
#define On 64
#define Hn 128
#define Wn 128
#define KK 9

// Scratch (device globals: no allocation allowed)
__device__ float g_xT[(size_t)Bn * Hn * Wn * Cn];     // x transposed to NHWC, 16 MB
__device__ float g_off[(size_t)Bn * Hn * Wn * 18];    // offsets, pixel-major [pix][18]
__device__ float g_w2[KK * Cn * On];                  // main weight as [k][c][o]

// ---------------------------------------------------------------------------
// Kernel 1: NCHW -> NHWC transpose of x
// grid (W/32, C/32, B*H), block (32, 8)
// ---------------------------------------------------------------------------
__global__ void transpose_k(const float* __restrict__ x) {
    __shared__ float tile[32][33];
    int w0 = blockIdx.x * 32;
    int c0 = blockIdx.y * 32;
    int bh = blockIdx.z;
    int b = bh >> 7, h = bh & 127;
    int tx = threadIdx.x, ty = threadIdx.y;
#pragma unroll
    for (int i = 0; i < 4; i++) {
        int c = c0 + ty + i * 8;
        tile[ty + i * 8][tx] = x[(((size_t)b * Cn + c) * Hn + h) * Wn + (w0 + tx)];
    }
    __syncthreads();
#pragma unroll
    for (int i = 0; i < 4; i++) {
        int w = w0 + ty + i * 8;
        g_xT[(((size_t)b * Hn + h) * Wn + w) * Cn + (c0 + tx)] = tile[tx][ty + i * 8];
    }
}

// ---------------------------------------------------------------------------
// Kernel 2: reorganize main weight (O,C,3,3) -> g_w2[k][c][o]
// ---------------------------------------------------------------------------
__global__ void prep_w_k(const float* __restrict__ weight) {
    int d = blockIdx.x * blockDim.x + threadIdx.x;
    if (d >= KK * Cn * On) return;
    int k = d >> 12;          // Cn*On = 4096
    int rem = d & 4095;
    int c = rem >> 6;
    int o = rem & 63;
    g_w2[d] = weight[(o * Cn + c) * KK + k];
}

// ---------------------------------------------------------------------------
// Kernel 3: offset conv (3x3 SAME, 64 -> 18 channels), reads NHWC x
// One thread per pixel. Weights staged in smem as wS[(tap*64+c)*18 + ch].
// grid 512, block 128
// ---------------------------------------------------------------------------
__global__ __launch_bounds__(128) void offset_conv_k(
    const float* __restrict__ offset_w,   // (18, 64, 3, 3)
    const float* __restrict__ offset_b)   // (18,)
{
    __shared__ float wS[KK * Cn * 18];    // 41472 B

    int tid = threadIdx.x;
    for (int s = tid; s < KK * Cn * 18; s += 128) {
        int ch = s % 18;
        int t2 = s / 18;
        int c = t2 & 63;
        int tap = t2 >> 6;
        wS[s] = offset_w[(ch * Cn + c) * KK + tap];
    }
    __syncthreads();

    int pid = blockIdx.x * 128 + tid;     // pixel id
    int b = pid >> 14;
    int y = (pid >> 7) & 127;
    int xw = pid & 127;

    float acc[18];
#pragma unroll
    for (int j = 0; j < 18; j++) acc[j] = offset_b[j];

    for (int ky = 0; ky < 3; ky++) {
        int yy = y - 1 + ky;
        if (yy < 0 || yy >= Hn) continue;
        for (int kx = 0; kx < 3; kx++) {
            int xx = xw - 1 + kx;
            if (xx < 0 || xx >= Wn) continue;
            int tap = ky * 3 + kx;
            const float* xp = g_xT + (((size_t)b * Hn + yy) * Wn + xx) * Cn;
            for (int c = 0; c < Cn; c += 4) {
                float4 xv = *(const float4*)(xp + c);
                const float* wp = &wS[(tap * Cn + c) * 18];
#pragma unroll
                for (int j = 0; j < 18; j++) {
                    acc[j] += xv.x * wp[j] + xv.y * wp[j + 18]
                            + xv.z * wp[j + 36] + xv.w * wp[j + 54];
                }
            }
        }
    }

    float* op = g_off + (size_t)pid * 18;
#pragma unroll
    for (int j = 0; j < 18; j++) op[j] = acc[j];
}

// ---------------------------------------------------------------------------
// Kernel 4: deformable conv. CTA = 32 pixels (8w x 4h) x 64 outputs.
// Per tap k: gather bilinear samples S_k[32][64] to smem (NHWC float4 loads),
// stage W_k[64][64] to smem, rank-64 update with 2px x 4o register tiles.
// grid (16, 32, 4), block 256
// ---------------------------------------------------------------------------
#define S_STRIDE 72   // 64 + 8 pad; keeps float4 alignment (72*4 % 16 == 0)

__global__ __launch_bounds__(256) void deform_k(
    const float* __restrict__ bias,
    float* __restrict__ out)
{
    __shared__ float sS[32 * S_STRIDE];   // samples  [p][c]
    __shared__ float sW[Cn * On];         // W_k      [c][o] (reused for epilogue)

    int tid = threadIdx.x;
    int x0t = blockIdx.x * 8;
    int y0t = blockIdx.y * 4;
    int b = blockIdx.z;

    // gather-phase mapping: 8 threads per pixel
    int gp = tid >> 3;            // pixel 0..31
    int lane8 = tid & 7;          // channel group
    int c0 = lane8 * 8;
    int glw = gp & 7, glh = gp >> 3;
    int gx = x0t + glw, gy = y0t + glh;
    int gpix = (b * Hn + gy) * Wn + gx;

    // gemm-phase mapping: 2 px x 4 o per thread
    int p0 = (tid >> 4) * 2;
    int o0 = (tid & 15) * 4;

    float4 acc0 = make_float4(0.f, 0.f, 0.f, 0.f);
    float4 acc1 = make_float4(0.f, 0.f, 0.f, 0.f);

    for (int k = 0; k < KK; k++) {
        __syncthreads();   // prior iteration done reading sS / sW

        // --- stage W_k[c][o] ---
        {
            const float4* src = (const float4*)(g_w2 + k * Cn * On);
            float4* dst = (float4*)sW;
#pragma unroll
            for (int r = 0; r < 4; r++) dst[tid + r * 256] = src[tid + r * 256];
        }

        // --- gather S_k ---
        {
            int ky = k / 3, kx = k - ky * 3;
            float offY = g_off[(size_t)gpix * 18 + 2 * k];
            float offX = g_off[(size_t)gpix * 18 + 2 * k + 1];
            float py = (float)(gy - 1 + ky) + offY;
            float px = (float)(gx - 1 + kx) + offX;
            float fy0 = floorf(py), fx0 = floorf(px);
            float wy1 = py - fy0, wx1 = px - fx0;
            float wy0 = 1.f - wy1, wx0 = 1.f - wx1;
            int iy0 = (int)fy0, ix0 = (int)fx0;
            int iy1 = iy0 + 1, ix1 = ix0 + 1;
            bool vy0 = (iy0 >= 0) & (iy0 < Hn);
            bool vy1 = (iy1 >= 0) & (iy1 < Hn);
            bool vx0 = (ix0 >= 0) & (ix0 < Wn);
            bool vx1 = (ix1 >= 0) & (ix1 < Wn);
            int cy0 = min(max(iy0, 0), Hn - 1);
            int cy1 = min(max(iy1, 0), Hn - 1);
            int cx0 = min(max(ix0, 0), Wn - 1);
            int cx1 = min(max(ix1, 0), Wn - 1);

            float4 r0 = make_float4(0.f, 0.f, 0.f, 0.f);
            float4 r1 = make_float4(0.f, 0.f, 0.f, 0.f);

            const float* xb = g_xT + (size_t)b * Hn * Wn * Cn;
#define CORNER(vy, vx, cy, cx, ww)                                          \
            if ((vy) & (vx)) {                                              \
                const float4* pp = (const float4*)(xb + ((size_t)(cy) * Wn + (cx)) * Cn + c0); \
                float4 a = pp[0]; float4 bb = pp[1]; float w_ = (ww);       \
                r0.x += w_ * a.x;  r0.y += w_ * a.y;                        \
                r0.z += w_ * a.z;  r0.w += w_ * a.w;                        \
                r1.x += w_ * bb.x; r1.y += w_ * bb.y;                       \
                r1.z += w_ * bb.z; r1.w += w_ * bb.w;                       \
            }
            CORNER(vy0, vx0, cy0, cx0, wy0 * wx0)
            CORNER(vy0, vx1, cy0, cx1, wy0 * wx1)
            CORNER(vy1, vx0, cy1, cx0, wy1 * wx0)
            CORNER(vy1, vx1, cy1, cx1, wy1 * wx1)
#undef CORNER
            *(float4*)(sS + gp * S_STRIDE + c0) = r0;
            *(float4*)(sS + gp * S_STRIDE + c0 + 4) = r1;
        }

        __syncthreads();

        // --- rank-64 update ---
        const float* sp0 = sS + p0 * S_STRIDE;
        const float* sp1 = sp0 + S_STRIDE;
#pragma unroll 8
        for (int c = 0; c < Cn; c++) {
            float a0 = sp0[c];
            float a1 = sp1[c];
            float4 bw = *(const float4*)(sW + c * On + o0);
            acc0.x += a0 * bw.x; acc0.y += a0 * bw.y;
            acc0.z += a0 * bw.z; acc0.w += a0 * bw.w;
            acc1.x += a1 * bw.x; acc1.y += a1 * bw.y;
            acc1.z += a1 * bw.z; acc1.w += a1 * bw.w;
        }
    }

    // --- epilogue: stage via smem (reuse sW) for coalesced NCHW stores ---
    __syncthreads();
    sW[(o0 + 0) * 32 + p0] = acc0.x;
    sW[(o0 + 1) * 32 + p0] = acc0.y;
    sW[(o0 + 2) * 32 + p0] = acc0.z;
    sW[(o0 + 3) * 32 + p0] = acc0.w;
    sW[(o0 + 0) * 32 + p0 + 1] = acc1.x;
    sW[(o0 + 1) * 32 + p0 + 1] = acc1.y;
    sW[(o0 + 2) * 32 + p0 + 1] = acc1.z;
    sW[(o0 + 3) * 32 + p0 + 1] = acc1.w;
    __syncthreads();

#pragma unroll
    for (int r = 0; r < 8; r++) {
        int i = r * 256 + tid;        // 0..2047
        int o = i >> 5;
        int p = i & 31;
        int lw = p & 7, lh = p >> 3;
        float v = sW[i] + bias[o];
        out[(((size_t)b * On + o) * Hn + (y0t + lh)) * Wn + (x0t + lw)] = v;
    }
}

// ---------------------------------------------------------------------------
extern "C" void kernel_launch(void* const* d_in, const int* in_sizes, int n_in,
                              void* d_out, int out_size) {
    const float* x        = (const float*)d_in[0];   // (4,64,128,128)
    const float* offset_w = (const float*)d_in[1];   // (18,64,3,3)
    const float* offset_b = (const float*)d_in[2];   // (18,)
    const float* weight   = (const float*)d_in[3];   // (64,64,3,3)
    const float* bias     = (const float*)d_in[4];   // (64,)
    float* out = (float*)d_out;                      // (4,64,128,128)

    transpose_k<<<dim3(Wn / 32, Cn / 32, Bn * Hn), dim3(32, 8)>>>(x);
    prep_w_k<<<(KK * Cn * On + 255) / 256, 256>>>(weight);
    offset_conv_k<<<(Bn * Hn * Wn) / 128, 128>>>(offset_w, offset_b);
    deform_k<<<dim3(Wn / 8, Hn / 4, Bn), 256>>>(bias, out);
}